// round 10
// baseline (speedup 1.0000x reference)
#include <cuda_runtime.h>
#include <math.h>
#include <stdint.h>

#define Nn 8192
#define Dd 64
#define IN_F 128
#define TI 128
#define TJ 64
#define SPLITS 16
#define JCH (Nn / SPLITS)     // 512
#define NTILE (JCH / TJ)      // 8
#define LOG2E 1.4426950408889634f

#define BITS_OFF 32768        // smem: 2x16KB B planes, then 2x1KB mask blocks

// ---------------- device scratch ---------------------------------------------
__device__ float g_xw_s[Nn * Dd];
__device__ float g_xw_t[Nn * Dd];
__device__ float g_s1[Nn], g_s2[Nn], g_t1[Nn], g_t2[Nn];   // pre-scaled by log2e
__device__ float g_max2[2];
__device__ unsigned short g_xT_hi[2][Dd * Nn];   // [side][d][j]
__device__ unsigned short g_xT_lo[2][Dd * Nn];
__device__ float g_pnum[2 * SPLITS * Nn * Dd];
__device__ float g_pden[2 * SPLITS * Nn];
__device__ uint32_t g_adjB[(size_t)Nn * (Nn / 32)];   // 8 MB bit-packed adjacency

// ---------------- helpers -----------------------------------------------------
__device__ __forceinline__ uint32_t smem_u32(const void* p) {
    uint32_t a;
    asm("{ .reg .u64 t; cvta.to.shared.u64 t, %1; cvt.u32.u64 %0, t; }" : "=r"(a) : "l"(p));
    return a;
}
__device__ __forceinline__ float leaky(float z) { return fmaxf(z, 0.01f * z); }
__device__ __forceinline__ float ex2(float x) {
    float r; asm("ex2.approx.f32 %0, %1;" : "=f"(r) : "f"(x)); return r;
}
__device__ __forceinline__ uint32_t bfpack(float w0, float w1) {
    uint32_t r; asm("cvt.rn.bf16x2.f32 %0, %1, %2;" : "=r"(r) : "f"(w1), "f"(w0)); return r;
}
__device__ __forceinline__ void split_bf16(float v, unsigned short& hi, unsigned short& lo) {
    asm("cvt.rn.bf16.f32 %0, %1;" : "=h"(hi) : "f"(v));
    float hf = __uint_as_float(((uint32_t)hi) << 16);
    float r = v - hf;
    asm("cvt.rn.bf16.f32 %0, %1;" : "=h"(lo) : "f"(r));
}
__device__ __forceinline__ void ldsm4(uint32_t* r, uint32_t addr) {
    asm volatile("ldmatrix.sync.aligned.m8n8.x4.shared.b16 {%0,%1,%2,%3}, [%4];"
        : "=r"(r[0]), "=r"(r[1]), "=r"(r[2]), "=r"(r[3]) : "r"(addr));
}
__device__ __forceinline__ void mma16816(float* d, const uint32_t* a, uint32_t b0, uint32_t b1) {
    asm volatile(
        "mma.sync.aligned.m16n8k16.row.col.f32.bf16.bf16.f32 "
        "{%0,%1,%2,%3},{%4,%5,%6,%7},{%8,%9},{%0,%1,%2,%3};"
        : "+f"(d[0]), "+f"(d[1]), "+f"(d[2]), "+f"(d[3])
        : "r"(a[0]), "r"(a[1]), "r"(a[2]), "r"(a[3]), "r"(b0), "r"(b1));
}
__device__ __forceinline__ void cpa16(uint32_t d, const void* s) {
    asm volatile("cp.async.cg.shared.global [%0], [%1], 16;" :: "r"(d), "l"(s));
}
__device__ __forceinline__ void cpa8(uint32_t d, const void* s) {
    asm volatile("cp.async.ca.shared.global [%0], [%1], 8;" :: "r"(d), "l"(s));
}
#define CP_COMMIT() asm volatile("cp.async.commit_group;" ::: "memory")
#define CP_WAIT0()  asm volatile("cp.async.wait_group 0;" ::: "memory")

// masked softmax weight (log2-domain inputs, mask from bit)
__device__ __forceinline__ float wgen(float s, float m, float t, uint32_t q, int bit) {
    float z = s + t;
    float w = ex2(fmaxf(z, 0.01f * z) - m);
    return ((q >> bit) & 1u) ? w : 0.f;
}

// ---------------- P0: pack adjacency rows to bits ----------------------------
__global__ void pack_kernel(const int* __restrict__ adj) {
    int i = blockIdx.x;
    int w8 = threadIdx.x >> 5, lane = threadIdx.x & 31;
    const int* row = adj + (size_t)i * Nn;
    uint32_t mine = 0;
    #pragma unroll 4
    for (int k = 0; k < 32; k++) {
        int word = w8 * 32 + k;
        uint32_t b = __ballot_sync(0xffffffffu, row[word * 32 + lane] > 0);
        if (lane == k) mine = b;
    }
    g_adjB[(size_t)i * (Nn / 32) + w8 * 32 + lane] = mine;
}

// ---------------- P1: xw = x @ W + bf16 planes + a-projections (fused) ------
__global__ void proj_kernel(const float* __restrict__ xs, const float* __restrict__ xt,
                            const float* __restrict__ ws, const float* __restrict__ wt,
                            const float* __restrict__ av) {
    int y = blockIdx.y;
    const float* x = y ? xt : xs;
    const float* W = y ? wt : ws;
    float* out = y ? g_xw_t : g_xw_s;

    __shared__ float Wsm[IN_F * Dd];
    __shared__ float xsm[16 * IN_F];
    __shared__ float s_red[8][4][2];   // [warp][k][plane]

    int tid = threadIdx.x;
    const float4* W4 = (const float4*)W;
    float4* Ws4 = (float4*)Wsm;
    for (int k = tid; k < IN_F * Dd / 4; k += 256) Ws4[k] = W4[k];

    int r0 = blockIdx.x * 16;
    const float4* x4 = (const float4*)(x + r0 * IN_F);
    float4* xs4 = (float4*)xsm;
    for (int k = tid; k < 16 * IN_F / 4; k += 256) xs4[k] = x4[k];
    __syncthreads();

    int c = tid & 63, rq = tid >> 6;
    float acc[4] = {0.f, 0.f, 0.f, 0.f};
    #pragma unroll 4
    for (int kk = 0; kk < IN_F; kk++) {
        float wv = Wsm[kk * Dd + c];
        #pragma unroll
        for (int k = 0; k < 4; k++)
            acc[k] += xsm[(rq + 4 * k) * IN_F + kk] * wv;
    }
    #pragma unroll
    for (int k = 0; k < 4; k++) {
        int row = r0 + rq + 4 * k;
        float v = acc[k];
        out[row * Dd + c] = v;
        unsigned short hi, lo;
        split_bf16(v, hi, lo);
        g_xT_hi[y][(size_t)c * Nn + row] = hi;
        g_xT_lo[y][(size_t)c * Nn + row] = lo;
    }

    // fused a-projection: row dots with a1=av[0..63], a2=av[64..127]
    float a1c = av[c], a2c = av[64 + c];
    int w = tid >> 5, lane = tid & 31;
    #pragma unroll
    for (int k = 0; k < 4; k++) {
        float p1 = acc[k] * a1c;
        float p2 = acc[k] * a2c;
        #pragma unroll
        for (int o = 16; o; o >>= 1) {
            p1 += __shfl_down_sync(0xffffffffu, p1, o);
            p2 += __shfl_down_sync(0xffffffffu, p2, o);
        }
        if (lane == 0) { s_red[w][k][0] = p1; s_red[w][k][1] = p2; }
    }
    __syncthreads();
    if (tid < 32) {
        int m = tid >> 3, k = (tid >> 1) & 3, pl = tid & 1;
        int row = r0 + m + 4 * k;
        float val = (s_red[2 * m][k][pl] + s_red[2 * m + 1][k][pl]) * LOG2E;
        if (y == 0) { if (pl == 0) g_s1[row] = val; else g_s2[row] = val; }
        else        { if (pl == 0) g_t1[row] = val; else g_t2[row] = val; }
    }
}

// ---------------- P3: maxes ---------------------------------------------------
__global__ void max_kernel() {
    __shared__ float sm[512];
    int tid = threadIdx.x;
    float m1 = -1e30f, m2 = -1e30f;
    for (int i = tid; i < Nn; i += 256) {
        m1 = fmaxf(m1, g_t2[i]);
        m2 = fmaxf(m2, g_s2[i]);
    }
    sm[tid] = m1; sm[256 + tid] = m2;
    __syncthreads();
    for (int s = 128; s; s >>= 1) {
        if (tid < s) {
            sm[tid]       = fmaxf(sm[tid],       sm[tid + s]);
            sm[256 + tid] = fmaxf(sm[256 + tid], sm[256 + tid + s]);
        }
        __syncthreads();
    }
    if (tid == 0) { g_max2[0] = sm[0]; g_max2[1] = sm[256]; }
}

// ---------------- main attention: cp.async staging + bitmask -----------------
__global__ void __launch_bounds__(256, 3)
attn_kernel() {
    __shared__ __align__(16) char smc[32768 + 2048];
    uint32_t smb = smem_u32(smc);

    int p = blockIdx.y, sp = blockIdx.z;
    int i0 = blockIdx.x * TI;
    int jbase = sp * JCH;
    const float* sv = p ? g_t1 : g_s1;
    const float* tv = p ? g_s2 : g_t2;
    const unsigned short* XH = g_xT_hi[p];
    const unsigned short* XL = g_xT_lo[p];
    float M = g_max2[p];

    int tid = threadIdx.x, wid = tid >> 5, lane = tid & 31;
    int r = lane >> 2, c = lane & 3;
    int iA = i0 + wid * 16 + r;
    int iB = iA + 8;

    float sA = sv[iA], sB = sv[iB];
    float mA = leaky(sA + M), mB = leaky(sB + M);

    // B ldmatrix addressing (XOR swizzle: col ^ ((row&7)<<4))
    uint32_t bSel = ((lane >> 3) & 1) * 16;
    uint32_t bSwz = (lane & 7) << 4;
    uint32_t bBase = smb + ((lane & 7) + ((lane >> 4) & 1) * 8) * 128;

    // B staging indices
    int sd = tid >> 2, scc = tid & 3;
    uint32_t sSwz = (sd & 7) << 4;
    uint32_t sRow = sd * 128;
    uint32_t so1 = sRow + ((scc * 16) ^ sSwz);
    uint32_t so2 = sRow + (((scc + 4) * 16) ^ sSwz);

    const uint32_t ONE2 = 0x3F803F80u;   // bf16x2 {1.0, 1.0}
    const uint32_t WDS = Nn / 32;

    float acc[8][4];
    float den[4];
    #pragma unroll
    for (int n = 0; n < 8; n++)
        #pragma unroll
        for (int q = 0; q < 4; q++) acc[n][q] = 0.f;
    #pragma unroll
    for (int q = 0; q < 4; q++) den[q] = 0.f;

    // ---- stage tile 0 into buffer 0 (cp.async) ----
    {
        const char* srch = (const char*)(XH + (size_t)sd * Nn + jbase);
        const char* srcl = (const char*)(XL + (size_t)sd * Nn + jbase);
        cpa16(smb + so1,        srch + scc * 16);
        cpa16(smb + so2,        srch + (scc + 4) * 16);
        cpa16(smb + 8192 + so1, srcl + scc * 16);
        cpa16(smb + 8192 + so2, srcl + (scc + 4) * 16);
        if (p == 0) {
            if (tid < TI) cpa8(smb + BITS_OFF + tid * 8,
                               g_adjB + (size_t)(i0 + tid) * WDS + (jbase >> 5));
        } else {
            if (tid < TJ) cpa16(smb + BITS_OFF + tid * 16,
                                g_adjB + (size_t)(jbase + tid) * WDS + (i0 >> 5));
        }
        CP_COMMIT();
        CP_WAIT0();
    }
    __syncthreads();

    for (int jt = 0; jt < NTILE; jt++) {
        int b = jt & 1;
        int j0 = jbase + jt * TJ;
        uint32_t bufB = bBase + b * 16384;
        const char* bitsCur = smc + BITS_OFF + b * 1024;

        // ---- prefetch next tile into the other buffer (async) ----
        if (jt + 1 < NTILE) {
            int jn = j0 + TJ;
            uint32_t ob = (b ^ 1);
            uint32_t obuf = ob * 16384;
            const char* srch = (const char*)(XH + (size_t)sd * Nn + jn);
            const char* srcl = (const char*)(XL + (size_t)sd * Nn + jn);
            cpa16(smb + obuf + so1,        srch + scc * 16);
            cpa16(smb + obuf + so2,        srch + (scc + 4) * 16);
            cpa16(smb + obuf + 8192 + so1, srcl + scc * 16);
            cpa16(smb + obuf + 8192 + so2, srcl + (scc + 4) * 16);
            if (p == 0) {
                if (tid < TI) cpa8(smb + BITS_OFF + ob * 1024 + tid * 8,
                                   g_adjB + (size_t)(i0 + tid) * WDS + (jn >> 5));
            } else {
                if (tid < TJ) cpa16(smb + BITS_OFF + ob * 1024 + tid * 16,
                                    g_adjB + (size_t)(jn + tid) * WDS + (i0 >> 5));
            }
            CP_COMMIT();
        }

        // ---- mask words for this tile ----
        uint2 vA, vB;
        int wsel = wid >> 1;
        int bitA = ((wid & 1) << 4) + r;
        if (p == 0) {
            vA = *(const uint2*)(bitsCur + (wid * 16 + r) * 8);
            vB = *(const uint2*)(bitsCur + (wid * 16 + r + 8) * 8);
        }

        // ---- per K-chunk: build A frags in regs, mma ----
        #pragma unroll
        for (int k = 0; k < 4; k++) {
            int jc = j0 + 16 * k + 2 * c;
            float2 t12 = *(const float2*)(tv + jc);
            float2 t34 = *(const float2*)(tv + jc + 8);

            float w0, w1, w2, w3, w4, w5, w6, w7;
            if (p == 0) {
                uint32_t qA = (k < 2) ? vA.x : vA.y;
                uint32_t qB = (k < 2) ? vB.x : vB.y;
                int b0 = ((k & 1) << 4) + 2 * c;
                w0 = wgen(sA, mA, t12.x, qA, b0);
                w1 = wgen(sA, mA, t12.y, qA, b0 + 1);
                w2 = wgen(sA, mA, t34.x, qA, b0 + 8);
                w3 = wgen(sA, mA, t34.y, qA, b0 + 9);
                w4 = wgen(sB, mB, t12.x, qB, b0);
                w5 = wgen(sB, mB, t12.y, qB, b0 + 1);
                w6 = wgen(sB, mB, t34.x, qB, b0 + 8);
                w7 = wgen(sB, mB, t34.y, qB, b0 + 9);
            } else {
                int rowb = 16 * k + 2 * c;
                uint32_t q0 = *(const uint32_t*)(bitsCur + (rowb    ) * 16 + wsel * 4);
                uint32_t q1 = *(const uint32_t*)(bitsCur + (rowb + 1) * 16 + wsel * 4);
                uint32_t q2 = *(const uint32_t*)(bitsCur + (rowb + 8) * 16 + wsel * 4);
                uint32_t q3 = *(const uint32_t*)(bitsCur + (rowb + 9) * 16 + wsel * 4);
                w0 = wgen(sA, mA, t12.x, q0, bitA);
                w1 = wgen(sA, mA, t12.y, q1, bitA);
                w2 = wgen(sA, mA, t34.x, q2, bitA);
                w3 = wgen(sA, mA, t34.y, q3, bitA);
                w4 = wgen(sB, mB, t12.x, q0, bitA + 8);
                w5 = wgen(sB, mB, t12.y, q1, bitA + 8);
                w6 = wgen(sB, mB, t34.x, q2, bitA + 8);
                w7 = wgen(sB, mB, t34.y, q3, bitA + 8);
            }

            uint32_t ah[4], al[4];
            ah[0] = bfpack(w0, w1);
            ah[1] = bfpack(w4, w5);
            ah[2] = bfpack(w2, w3);
            ah[3] = bfpack(w6, w7);
            {
                float h;
                h = __uint_as_float(ah[0] << 16);          float e0 = w0 - h;
                h = __uint_as_float(ah[0] & 0xFFFF0000u);  float e1 = w1 - h;
                al[0] = bfpack(e0, e1);
                h = __uint_as_float(ah[1] << 16);          e0 = w4 - h;
                h = __uint_as_float(ah[1] & 0xFFFF0000u);  e1 = w5 - h;
                al[1] = bfpack(e0, e1);
                h = __uint_as_float(ah[2] << 16);          e0 = w2 - h;
                h = __uint_as_float(ah[2] & 0xFFFF0000u);  e1 = w3 - h;
                al[2] = bfpack(e0, e1);
                h = __uint_as_float(ah[3] << 16);          e0 = w6 - h;
                h = __uint_as_float(ah[3] & 0xFFFF0000u);  e1 = w7 - h;
                al[3] = bfpack(e0, e1);
            }

            mma16816(den, ah, ONE2, ONE2);
            mma16816(den, al, ONE2, ONE2);

            #pragma unroll
            for (int nn = 0; nn < 4; nn++) {
                uint32_t bh[4], bl[4];
                uint32_t boff = nn * 2048 + ((bSel + 32 * k) ^ bSwz);
                ldsm4(bh, bufB + boff);
                ldsm4(bl, bufB + 8192 + boff);
                mma16816(acc[2 * nn],     ah, bh[0], bh[1]);
                mma16816(acc[2 * nn + 1], ah, bh[2], bh[3]);
                mma16816(acc[2 * nn],     ah, bl[0], bl[1]);
                mma16816(acc[2 * nn + 1], ah, bl[2], bl[3]);
                mma16816(acc[2 * nn],     al, bh[0], bh[1]);
                mma16816(acc[2 * nn + 1], al, bh[2], bh[3]);
            }
        }
        CP_WAIT0();
        __syncthreads();
    }

    // ---- write partials ----
    int buf = p * SPLITS + sp;
    int tg = lane & 3;
    float* nump = g_pnum + (size_t)buf * Nn * Dd;
    #pragma unroll
    for (int n = 0; n < 8; n++) {
        int col = n * 8 + tg * 2;
        *(float2*)(nump + (size_t)iA * Dd + col) = make_float2(acc[n][0], acc[n][1]);
        *(float2*)(nump + (size_t)iB * Dd + col) = make_float2(acc[n][2], acc[n][3]);
    }
    if (tg == 0) {
        g_pden[(size_t)buf * Nn + iA] = den[0];
        g_pden[(size_t)buf * Nn + iB] = den[2];
    }
}

// ---------------- finish: sum partials, normalize, bias + ELU ----------------
__global__ void finish_kernel(const float* __restrict__ bs, const float* __restrict__ bt,
                              float* __restrict__ out) {
    int warp = threadIdx.x >> 5, lane = threadIdx.x & 31;
    int rg = blockIdx.x * 8 + warp;
    int p = rg >> 13;
    int i = rg & (Nn - 1);
    const float* bias = p ? bt : bs;

    float2 acc = make_float2(0.f, 0.f);
    #pragma unroll
    for (int s = 0; s < SPLITS; s++) {
        const float2* np = (const float2*)(g_pnum + ((size_t)(p * SPLITS + s) * Nn + i) * Dd);
        float2 v = np[lane];
        acc.x += v.x; acc.y += v.y;
    }
    float den = (lane < SPLITS) ? g_pden[(size_t)(p * SPLITS + lane) * Nn + i] : 0.f;
    #pragma unroll
    for (int o = 16; o; o >>= 1) den += __shfl_xor_sync(0xffffffffu, den, o);
    float inv = 1.f / den;

    float v0 = acc.x * inv + bias[2 * lane];
    float v1 = acc.y * inv + bias[2 * lane + 1];
    v0 = (v0 > 0.f) ? v0 : expm1f(v0);
    v1 = (v1 > 0.f) ? v1 : expm1f(v1);
    ((float2*)(out + (size_t)rg * Dd))[lane] = make_float2(v0, v1);
}

// ---------------- launch ------------------------------------------------------
extern "C" void kernel_launch(void* const* d_in, const int* in_sizes, int n_in,
                              void* d_out, int out_size) {
    const float* xs  = (const float*)d_in[0];
    const float* xt  = (const float*)d_in[1];
    const int*   adj = (const int*)  d_in[2];
    const float* ws  = (const float*)d_in[3];
    const float* wt  = (const float*)d_in[4];
    const float* a   = (const float*)d_in[5];
    const float* bs  = (const float*)d_in[6];
    const float* bt  = (const float*)d_in[7];
    float* out = (float*)d_out;   // [2, 8192, 64]

    pack_kernel<<<Nn, 256>>>(adj);
    proj_kernel<<<dim3(Nn / 16, 2), 256>>>(xs, xt, ws, wt, a);
    max_kernel<<<1, 256>>>();
    attn_kernel<<<dim3(Nn / TI, 2, SPLITS), 256>>>();
    finish_kernel<<<(2 * Nn) / 8, 256>>>(bs, bt, out);
}

// round 12
// speedup vs baseline: 1.1128x; 1.1128x over previous
#include <cuda_runtime.h>
#include <math.h>
#include <stdint.h>

#define Nn 8192
#define Dd 64
#define IN_F 128
#define TI 128
#define TJ 64
#define SPLITS 16
#define JCH (Nn / SPLITS)     // 512
#define NTILE (JCH / TJ)      // 8
#define LOG2E 1.4426950408889634f

#define BITS_OFF 32768        // smem: 2x16KB B planes, then 2x1KB mask blocks

// ---------------- device scratch ---------------------------------------------
__device__ float g_xw_s[Nn * Dd];
__device__ float g_xw_t[Nn * Dd];
__device__ float g_s1[Nn], g_s2[Nn], g_t1[Nn], g_t2[Nn];   // pre-scaled by log2e
__device__ float g_fb2[2][Nn];   // exp2(t'_j)      for the "2" vectors (per source side y)
__device__ float g_fd2[2][Nn];   // exp2(0.01 t'_j)
__device__ float g_max2[2];
__device__ unsigned short g_xT_hi[2][Dd * Nn];   // fp16 planes [side][d][j]
__device__ unsigned short g_xT_lo[2][Dd * Nn];
__device__ float g_pnum[2 * SPLITS * Nn * Dd];
__device__ float g_pden[2 * SPLITS * Nn];
__device__ uint32_t g_adjB[(size_t)Nn * (Nn / 32)];   // 8 MB bit-packed adjacency

// ---------------- helpers -----------------------------------------------------
__device__ __forceinline__ uint32_t smem_u32(const void* p) {
    uint32_t a;
    asm("{ .reg .u64 t; cvta.to.shared.u64 t, %1; cvt.u32.u64 %0, t; }" : "=r"(a) : "l"(p));
    return a;
}
__device__ __forceinline__ float leaky(float z) { return fmaxf(z, 0.01f * z); }
__device__ __forceinline__ float ex2(float x) {
    float r; asm("ex2.approx.f32 %0, %1;" : "=f"(r) : "f"(x)); return r;
}
// pack {lo half = w0, hi half = w1} as fp16x2
__device__ __forceinline__ uint32_t hpack(float w0, float w1) {
    uint32_t r; asm("cvt.rn.f16x2.f32 %0, %1, %2;" : "=r"(r) : "f"(w1), "f"(w0)); return r;
}
__device__ __forceinline__ void split_f16(float v, unsigned short& hi, unsigned short& lo) {
    asm("cvt.rn.f16.f32 %0, %1;" : "=h"(hi) : "f"(v));
    float hf; asm("cvt.f32.f16 %0, %1;" : "=f"(hf) : "h"(hi));
    float r = v - hf;
    asm("cvt.rn.f16.f32 %0, %1;" : "=h"(lo) : "f"(r));
}
__device__ __forceinline__ void ldsm4(uint32_t* r, uint32_t addr) {
    asm volatile("ldmatrix.sync.aligned.m8n8.x4.shared.b16 {%0,%1,%2,%3}, [%4];"
        : "=r"(r[0]), "=r"(r[1]), "=r"(r[2]), "=r"(r[3]) : "r"(addr));
}
__device__ __forceinline__ void mma16816(float* d, const uint32_t* a, uint32_t b0, uint32_t b1) {
    asm volatile(
        "mma.sync.aligned.m16n8k16.row.col.f32.f16.f16.f32 "
        "{%0,%1,%2,%3},{%4,%5,%6,%7},{%8,%9},{%0,%1,%2,%3};"
        : "+f"(d[0]), "+f"(d[1]), "+f"(d[2]), "+f"(d[3])
        : "r"(a[0]), "r"(a[1]), "r"(a[2]), "r"(a[3]), "r"(b0), "r"(b1));
}
__device__ __forceinline__ void cpa16(uint32_t d, const void* s) {
    asm volatile("cp.async.cg.shared.global [%0], [%1], 16;" :: "r"(d), "l"(s));
}
__device__ __forceinline__ void cpa8(uint32_t d, const void* s) {
    asm volatile("cp.async.ca.shared.global [%0], [%1], 8;" :: "r"(d), "l"(s));
}
#define CP_COMMIT() asm volatile("cp.async.commit_group;" ::: "memory")
#define CP_WAIT0()  asm volatile("cp.async.wait_group 0;" ::: "memory")

// separable masked weight: w = (s+t>=0 ? E*fb : C*fd), masked by bit
__device__ __forceinline__ float wgen2(float s, float E, float C,
                                       float t, float fb, float fd,
                                       uint32_t q, int bit) {
    float z = s + t;
    float w = (z >= 0.f) ? (E * fb) : (C * fd);
    return ((q >> bit) & 1u) ? w : 0.f;
}

// ---------------- P0: pack adjacency rows to bits ----------------------------
__global__ void pack_kernel(const int* __restrict__ adj) {
    int i = blockIdx.x;
    int w8 = threadIdx.x >> 5, lane = threadIdx.x & 31;
    const int* row = adj + (size_t)i * Nn;
    uint32_t mine = 0;
    #pragma unroll 4
    for (int k = 0; k < 32; k++) {
        int word = w8 * 32 + k;
        uint32_t b = __ballot_sync(0xffffffffu, row[word * 32 + lane] > 0);
        if (lane == k) mine = b;
    }
    g_adjB[(size_t)i * (Nn / 32) + w8 * 32 + lane] = mine;
}

// ---------------- P1: xw = x @ W + fp16 planes + a-projections (fused) ------
__global__ void proj_kernel(const float* __restrict__ xs, const float* __restrict__ xt,
                            const float* __restrict__ ws, const float* __restrict__ wt,
                            const float* __restrict__ av) {
    int y = blockIdx.y;
    const float* x = y ? xt : xs;
    const float* W = y ? wt : ws;
    float* out = y ? g_xw_t : g_xw_s;

    __shared__ float Wsm[IN_F * Dd];
    __shared__ float xsm[16 * IN_F];
    __shared__ float s_red[8][4][2];   // [warp][k][plane]

    int tid = threadIdx.x;
    const float4* W4 = (const float4*)W;
    float4* Ws4 = (float4*)Wsm;
    for (int k = tid; k < IN_F * Dd / 4; k += 256) Ws4[k] = W4[k];

    int r0 = blockIdx.x * 16;
    const float4* x4 = (const float4*)(x + r0 * IN_F);
    float4* xs4 = (float4*)xsm;
    for (int k = tid; k < 16 * IN_F / 4; k += 256) xs4[k] = x4[k];
    __syncthreads();

    int c = tid & 63, rq = tid >> 6;
    float acc[4] = {0.f, 0.f, 0.f, 0.f};
    #pragma unroll 4
    for (int kk = 0; kk < IN_F; kk++) {
        float wv = Wsm[kk * Dd + c];
        #pragma unroll
        for (int k = 0; k < 4; k++)
            acc[k] += xsm[(rq + 4 * k) * IN_F + kk] * wv;
    }
    #pragma unroll
    for (int k = 0; k < 4; k++) {
        int row = r0 + rq + 4 * k;
        float v = acc[k];
        out[row * Dd + c] = v;
        unsigned short hi, lo;
        split_f16(v, hi, lo);
        g_xT_hi[y][(size_t)c * Nn + row] = hi;
        g_xT_lo[y][(size_t)c * Nn + row] = lo;
    }

    // fused a-projection: row dots with a1=av[0..63], a2=av[64..127]
    float a1c = av[c], a2c = av[64 + c];
    int w = tid >> 5, lane = tid & 31;
    #pragma unroll
    for (int k = 0; k < 4; k++) {
        float p1 = acc[k] * a1c;
        float p2 = acc[k] * a2c;
        #pragma unroll
        for (int o = 16; o; o >>= 1) {
            p1 += __shfl_down_sync(0xffffffffu, p1, o);
            p2 += __shfl_down_sync(0xffffffffu, p2, o);
        }
        if (lane == 0) { s_red[w][k][0] = p1; s_red[w][k][1] = p2; }
    }
    __syncthreads();
    if (tid < 32) {
        int m = tid >> 3, k = (tid >> 1) & 3, pl = tid & 1;
        int row = r0 + m + 4 * k;
        float val = (s_red[2 * m][k][pl] + s_red[2 * m + 1][k][pl]) * LOG2E;
        if (pl == 0) {
            if (y == 0) g_s1[row] = val; else g_t1[row] = val;
        } else {
            if (y == 0) g_s2[row] = val; else g_t2[row] = val;
            g_fb2[y][row] = ex2(val);
            g_fd2[y][row] = ex2(0.01f * val);
        }
    }
}

// ---------------- P3: maxes ---------------------------------------------------
__global__ void max_kernel() {
    __shared__ float sm[512];
    int tid = threadIdx.x;
    float m1 = -1e30f, m2 = -1e30f;
    for (int i = tid; i < Nn; i += 256) {
        m1 = fmaxf(m1, g_t2[i]);
        m2 = fmaxf(m2, g_s2[i]);
    }
    sm[tid] = m1; sm[256 + tid] = m2;
    __syncthreads();
    for (int s = 128; s; s >>= 1) {
        if (tid < s) {
            sm[tid]       = fmaxf(sm[tid],       sm[tid + s]);
            sm[256 + tid] = fmaxf(sm[256 + tid], sm[256 + tid + s]);
        }
        __syncthreads();
    }
    if (tid == 0) { g_max2[0] = sm[0]; g_max2[1] = sm[256]; }
}

// ---------------- main attention: separable exp + fp16 2-pass mma ------------
__global__ void __launch_bounds__(256, 3)
attn_kernel() {
    __shared__ __align__(16) char smc[32768 + 2048];
    uint32_t smb = smem_u32(smc);

    int p = blockIdx.y, sp = blockIdx.z;
    int i0 = blockIdx.x * TI;
    int jbase = sp * JCH;
    const float* sv = p ? g_t1 : g_s1;
    const float* tv = p ? g_s2 : g_t2;
    const float* fbv = g_fb2[p ^ 1];
    const float* fdv = g_fd2[p ^ 1];
    const unsigned short* XH = g_xT_hi[p];
    const unsigned short* XL = g_xT_lo[p];
    float M = g_max2[p];

    int tid = threadIdx.x, wid = tid >> 5, lane = tid & 31;
    int r = lane >> 2, c = lane & 3;
    int iA = i0 + wid * 16 + r;
    int iB = iA + 8;

    float sA = sv[iA], sB = sv[iB];
    float mA = leaky(sA + M), mB = leaky(sB + M);
    float EA = ex2(sA - mA), CA = ex2(0.01f * sA - mA);
    float EB = ex2(sB - mB), CB = ex2(0.01f * sB - mB);

    // B ldmatrix addressing (XOR swizzle: col ^ ((row&7)<<4))
    uint32_t bSel = ((lane >> 3) & 1) * 16;
    uint32_t bSwz = (lane & 7) << 4;
    uint32_t bBase = smb + ((lane & 7) + ((lane >> 4) & 1) * 8) * 128;

    // B staging indices
    int sd = tid >> 2, scc = tid & 3;
    uint32_t sSwz = (sd & 7) << 4;
    uint32_t sRow = sd * 128;
    uint32_t so1 = sRow + ((scc * 16) ^ sSwz);
    uint32_t so2 = sRow + (((scc + 4) * 16) ^ sSwz);

    const uint32_t ONE2 = 0x3C003C00u;   // fp16x2 {1.0, 1.0}
    const uint32_t WDS = Nn / 32;

    float acc[8][4];
    float den[4];
    #pragma unroll
    for (int n = 0; n < 8; n++)
        #pragma unroll
        for (int q = 0; q < 4; q++) acc[n][q] = 0.f;
    #pragma unroll
    for (int q = 0; q < 4; q++) den[q] = 0.f;

    // ---- stage tile 0 into buffer 0 (cp.async) ----
    {
        const char* srch = (const char*)(XH + (size_t)sd * Nn + jbase);
        const char* srcl = (const char*)(XL + (size_t)sd * Nn + jbase);
        cpa16(smb + so1,        srch + scc * 16);
        cpa16(smb + so2,        srch + (scc + 4) * 16);
        cpa16(smb + 8192 + so1, srcl + scc * 16);
        cpa16(smb + 8192 + so2, srcl + (scc + 4) * 16);
        if (p == 0) {
            if (tid < TI) cpa8(smb + BITS_OFF + tid * 8,
                               g_adjB + (size_t)(i0 + tid) * WDS + (jbase >> 5));
        } else {
            if (tid < TJ) cpa16(smb + BITS_OFF + tid * 16,
                                g_adjB + (size_t)(jbase + tid) * WDS + (i0 >> 5));
        }
        CP_COMMIT();
        CP_WAIT0();
    }
    __syncthreads();

    for (int jt = 0; jt < NTILE; jt++) {
        int b = jt & 1;
        int j0 = jbase + jt * TJ;
        uint32_t bufB = bBase + b * 16384;
        const char* bitsCur = smc + BITS_OFF + b * 1024;

        // ---- prefetch next tile into the other buffer (async) ----
        if (jt + 1 < NTILE) {
            int jn = j0 + TJ;
            uint32_t ob = (b ^ 1);
            uint32_t obuf = ob * 16384;
            const char* srch = (const char*)(XH + (size_t)sd * Nn + jn);
            const char* srcl = (const char*)(XL + (size_t)sd * Nn + jn);
            cpa16(smb + obuf + so1,        srch + scc * 16);
            cpa16(smb + obuf + so2,        srch + (scc + 4) * 16);
            cpa16(smb + obuf + 8192 + so1, srcl + scc * 16);
            cpa16(smb + obuf + 8192 + so2, srcl + (scc + 4) * 16);
            if (p == 0) {
                if (tid < TI) cpa8(smb + BITS_OFF + ob * 1024 + tid * 8,
                                   g_adjB + (size_t)(i0 + tid) * WDS + (jn >> 5));
            } else {
                if (tid < TJ) cpa16(smb + BITS_OFF + ob * 1024 + tid * 16,
                                    g_adjB + (size_t)(jn + tid) * WDS + (i0 >> 5));
            }
            CP_COMMIT();
        }

        // ---- mask words for this tile ----
        uint2 vA, vB;
        int wsel = wid >> 1;
        int bitA = ((wid & 1) << 4) + r;
        if (p == 0) {
            vA = *(const uint2*)(bitsCur + (wid * 16 + r) * 8);
            vB = *(const uint2*)(bitsCur + (wid * 16 + r + 8) * 8);
        }

        // ---- per K-chunk: build fp16 A frags in regs, mma ----
        #pragma unroll
        for (int k = 0; k < 4; k++) {
            int jc = j0 + 16 * k + 2 * c;
            float2 t12  = *(const float2*)(tv + jc);
            float2 t34  = *(const float2*)(tv + jc + 8);
            float2 fb12 = *(const float2*)(fbv + jc);
            float2 fb34 = *(const float2*)(fbv + jc + 8);
            float2 fd12 = *(const float2*)(fdv + jc);
            float2 fd34 = *(const float2*)(fdv + jc + 8);

            float w0, w1, w2, w3, w4, w5, w6, w7;
            if (p == 0) {
                uint32_t qA = (k < 2) ? vA.x : vA.y;
                uint32_t qB = (k < 2) ? vB.x : vB.y;
                int b0 = ((k & 1) << 4) + 2 * c;
                w0 = wgen2(sA, EA, CA, t12.x, fb12.x, fd12.x, qA, b0);
                w1 = wgen2(sA, EA, CA, t12.y, fb12.y, fd12.y, qA, b0 + 1);
                w2 = wgen2(sA, EA, CA, t34.x, fb34.x, fd34.x, qA, b0 + 8);
                w3 = wgen2(sA, EA, CA, t34.y, fb34.y, fd34.y, qA, b0 + 9);
                w4 = wgen2(sB, EB, CB, t12.x, fb12.x, fd12.x, qB, b0);
                w5 = wgen2(sB, EB, CB, t12.y, fb12.y, fd12.y, qB, b0 + 1);
                w6 = wgen2(sB, EB, CB, t34.x, fb34.x, fd34.x, qB, b0 + 8);
                w7 = wgen2(sB, EB, CB, t34.y, fb34.y, fd34.y, qB, b0 + 9);
            } else {
                int rowb = 16 * k + 2 * c;
                uint32_t q0 = *(const uint32_t*)(bitsCur + (rowb    ) * 16 + wsel * 4);
                uint32_t q1 = *(const uint32_t*)(bitsCur + (rowb + 1) * 16 + wsel * 4);
                uint32_t q2 = *(const uint32_t*)(bitsCur + (rowb + 8) * 16 + wsel * 4);
                uint32_t q3 = *(const uint32_t*)(bitsCur + (rowb + 9) * 16 + wsel * 4);
                w0 = wgen2(sA, EA, CA, t12.x, fb12.x, fd12.x, q0, bitA);
                w1 = wgen2(sA, EA, CA, t12.y, fb12.y, fd12.y, q1, bitA);
                w2 = wgen2(sA, EA, CA, t34.x, fb34.x, fd34.x, q2, bitA);
                w3 = wgen2(sA, EA, CA, t34.y, fb34.y, fd34.y, q3, bitA);
                w4 = wgen2(sB, EB, CB, t12.x, fb12.x, fd12.x, q0, bitA + 8);
                w5 = wgen2(sB, EB, CB, t12.y, fb12.y, fd12.y, q1, bitA + 8);
                w6 = wgen2(sB, EB, CB, t34.x, fb34.x, fd34.x, q2, bitA + 8);
                w7 = wgen2(sB, EB, CB, t34.y, fb34.y, fd34.y, q3, bitA + 8);
            }

            uint32_t ah[4];
            ah[0] = hpack(w0, w1);
            ah[1] = hpack(w4, w5);
            ah[2] = hpack(w2, w3);
            ah[3] = hpack(w6, w7);

            mma16816(den, ah, ONE2, ONE2);

            #pragma unroll
            for (int nn = 0; nn < 4; nn++) {
                uint32_t bh[4], bl[4];
                uint32_t boff = nn * 2048 + ((bSel + 32 * k) ^ bSwz);
                ldsm4(bh, bufB + boff);
                ldsm4(bl, bufB + 8192 + boff);
                mma16816(acc[2 * nn],     ah, bh[0], bh[1]);
                mma16816(acc[2 * nn + 1], ah, bh[2], bh[3]);
                mma16816(acc[2 * nn],     ah, bl[0], bl[1]);
                mma16816(acc[2 * nn + 1], ah, bl[2], bl[3]);
            }
        }
        CP_WAIT0();
        __syncthreads();
    }

    // ---- write partials ----
    int buf = p * SPLITS + sp;
    int tg = lane & 3;
    float* nump = g_pnum + (size_t)buf * Nn * Dd;
    #pragma unroll
    for (int n = 0; n < 8; n++) {
        int col = n * 8 + tg * 2;
        *(float2*)(nump + (size_t)iA * Dd + col) = make_float2(acc[n][0], acc[n][1]);
        *(float2*)(nump + (size_t)iB * Dd + col) = make_float2(acc[n][2], acc[n][3]);
    }
    if (tg == 0) {
        g_pden[(size_t)buf * Nn + iA] = den[0];
        g_pden[(size_t)buf * Nn + iB] = den[2];
    }
}

// ---------------- finish: sum partials, normalize, bias + ELU ----------------
__global__ void finish_kernel(const float* __restrict__ bs, const float* __restrict__ bt,
                              float* __restrict__ out) {
    int warp = threadIdx.x >> 5, lane = threadIdx.x & 31;
    int rg = blockIdx.x * 8 + warp;
    int p = rg >> 13;
    int i = rg & (Nn - 1);
    const float* bias = p ? bt : bs;

    float2 acc = make_float2(0.f, 0.f);
    #pragma unroll
    for (int s = 0; s < SPLITS; s++) {
        const float2* np = (const float2*)(g_pnum + ((size_t)(p * SPLITS + s) * Nn + i) * Dd);
        float2 v = np[lane];
        acc.x += v.x; acc.y += v.y;
    }
    float den = (lane < SPLITS) ? g_pden[(size_t)(p * SPLITS + lane) * Nn + i] : 0.f;
    #pragma unroll
    for (int o = 16; o; o >>= 1) den += __shfl_xor_sync(0xffffffffu, den, o);
    float inv = 1.f / den;

    float v0 = acc.x * inv + bias[2 * lane];
    float v1 = acc.y * inv + bias[2 * lane + 1];
    v0 = (v0 > 0.f) ? v0 : expm1f(v0);
    v1 = (v1 > 0.f) ? v1 : expm1f(v1);
    ((float2*)(out + (size_t)rg * Dd))[lane] = make_float2(v0, v1);
}

// ---------------- launch ------------------------------------------------------
extern "C" void kernel_launch(void* const* d_in, const int* in_sizes, int n_in,
                              void* d_out, int out_size) {
    const float* xs  = (const float*)d_in[0];
    const float* xt  = (const float*)d_in[1];
    const int*   adj = (const int*)  d_in[2];
    const float* ws  = (const float*)d_in[3];
    const float* wt  = (const float*)d_in[4];
    const float* a   = (const float*)d_in[5];
    const float* bs  = (const float*)d_in[6];
    const float* bt  = (const float*)d_in[7];
    float* out = (float*)d_out;   // [2, 8192, 64]

    pack_kernel<<<Nn, 256>>>(adj);
    proj_kernel<<<dim3(Nn / 16, 2), 256>>>(xs, xt, ws, wt, a);
    max_kernel<<<1, 256>>>();
    attn_kernel<<<dim3(Nn / TI, 2, SPLITS), 256>>>();
    finish_kernel<<<(2 * Nn) / 8, 256>>>(bs, bt, out);
}

// round 13
// speedup vs baseline: 1.2372x; 1.1118x over previous
#include <cuda_runtime.h>
#include <math.h>
#include <stdint.h>

#define Nn 8192
#define Dd 64
#define IN_F 128
#define TI 128
#define TJ 64
#define SPLITS 16
#define JCH (Nn / SPLITS)     // 512
#define NTILE (JCH / TJ)      // 8
#define LOG2E 1.4426950408889634f

#define BITS_OFF 16384        // smem: 2x8KB B planes, then 2x1KB mask blocks

// ---------------- device scratch ---------------------------------------------
__device__ float g_xw_s[Nn * Dd];
__device__ float g_xw_t[Nn * Dd];
__device__ float g_s1[Nn], g_s2[Nn], g_t1[Nn], g_t2[Nn];   // pre-scaled by log2e
__device__ float g_fb2[2][Nn];   // exp2(t'_j)
__device__ float g_fd2[2][Nn];   // exp2(0.01 t'_j)
__device__ float g_max2[2];
__device__ unsigned short g_xT_hi[2][Dd * Nn];   // fp16 plane [side][d][j]
__device__ float g_pnum[2 * SPLITS * Nn * Dd];
__device__ float g_pden[2 * SPLITS * Nn];
__device__ uint32_t g_adjB[(size_t)Nn * (Nn / 32)];   // 8 MB bit-packed adjacency

// ---------------- helpers -----------------------------------------------------
__device__ __forceinline__ uint32_t smem_u32(const void* p) {
    uint32_t a;
    asm("{ .reg .u64 t; cvta.to.shared.u64 t, %1; cvt.u32.u64 %0, t; }" : "=r"(a) : "l"(p));
    return a;
}
__device__ __forceinline__ float leaky(float z) { return fmaxf(z, 0.01f * z); }
__device__ __forceinline__ float ex2(float x) {
    float r; asm("ex2.approx.f32 %0, %1;" : "=f"(r) : "f"(x)); return r;
}
// pack {lo half = w0, hi half = w1} as fp16x2
__device__ __forceinline__ uint32_t hpack(float w0, float w1) {
    uint32_t r; asm("cvt.rn.f16x2.f32 %0, %1, %2;" : "=r"(r) : "f"(w1), "f"(w0)); return r;
}
__device__ __forceinline__ void ldsm4(uint32_t* r, uint32_t addr) {
    asm volatile("ldmatrix.sync.aligned.m8n8.x4.shared.b16 {%0,%1,%2,%3}, [%4];"
        : "=r"(r[0]), "=r"(r[1]), "=r"(r[2]), "=r"(r[3]) : "r"(addr));
}
__device__ __forceinline__ void mma16816(float* d, const uint32_t* a, uint32_t b0, uint32_t b1) {
    asm volatile(
        "mma.sync.aligned.m16n8k16.row.col.f32.f16.f16.f32 "
        "{%0,%1,%2,%3},{%4,%5,%6,%7},{%8,%9},{%0,%1,%2,%3};"
        : "+f"(d[0]), "+f"(d[1]), "+f"(d[2]), "+f"(d[3])
        : "r"(a[0]), "r"(a[1]), "r"(a[2]), "r"(a[3]), "r"(b0), "r"(b1));
}
__device__ __forceinline__ void cpa16(uint32_t d, const void* s) {
    asm volatile("cp.async.cg.shared.global [%0], [%1], 16;" :: "r"(d), "l"(s));
}
__device__ __forceinline__ void cpa8(uint32_t d, const void* s) {
    asm volatile("cp.async.ca.shared.global [%0], [%1], 8;" :: "r"(d), "l"(s));
}
#define CP_COMMIT() asm volatile("cp.async.commit_group;" ::: "memory")
#define CP_WAIT0()  asm volatile("cp.async.wait_group 0;" ::: "memory")

// separable masked weight: w = (s+t>=0 ? E*fb : C*fd), masked by bit
__device__ __forceinline__ float wgen2(float s, float E, float C,
                                       float t, float fb, float fd,
                                       uint32_t q, int bit) {
    float z = s + t;
    float w = (z >= 0.f) ? (E * fb) : (C * fd);
    return ((q >> bit) & 1u) ? w : 0.f;
}

// ---------------- P0: pack adjacency rows to bits ----------------------------
__global__ void pack_kernel(const int* __restrict__ adj) {
    int i = blockIdx.x;
    int w8 = threadIdx.x >> 5, lane = threadIdx.x & 31;
    const int* row = adj + (size_t)i * Nn;
    uint32_t mine = 0;
    #pragma unroll 4
    for (int k = 0; k < 32; k++) {
        int word = w8 * 32 + k;
        uint32_t b = __ballot_sync(0xffffffffu, row[word * 32 + lane] > 0);
        if (lane == k) mine = b;
    }
    g_adjB[(size_t)i * (Nn / 32) + w8 * 32 + lane] = mine;
}

// ---------------- P1: xw = x @ W + fp16 plane + a-projections (fused) -------
__global__ void proj_kernel(const float* __restrict__ xs, const float* __restrict__ xt,
                            const float* __restrict__ ws, const float* __restrict__ wt,
                            const float* __restrict__ av) {
    int y = blockIdx.y;
    const float* x = y ? xt : xs;
    const float* W = y ? wt : ws;
    float* out = y ? g_xw_t : g_xw_s;

    __shared__ float Wsm[IN_F * Dd];
    __shared__ float xsm[16 * IN_F];
    __shared__ float s_red[8][4][2];   // [warp][k][plane]

    int tid = threadIdx.x;
    const float4* W4 = (const float4*)W;
    float4* Ws4 = (float4*)Wsm;
    for (int k = tid; k < IN_F * Dd / 4; k += 256) Ws4[k] = W4[k];

    int r0 = blockIdx.x * 16;
    const float4* x4 = (const float4*)(x + r0 * IN_F);
    float4* xs4 = (float4*)xsm;
    for (int k = tid; k < 16 * IN_F / 4; k += 256) xs4[k] = x4[k];
    __syncthreads();

    int c = tid & 63, rq = tid >> 6;
    float acc[4] = {0.f, 0.f, 0.f, 0.f};
    #pragma unroll 4
    for (int kk = 0; kk < IN_F; kk++) {
        float wv = Wsm[kk * Dd + c];
        #pragma unroll
        for (int k = 0; k < 4; k++)
            acc[k] += xsm[(rq + 4 * k) * IN_F + kk] * wv;
    }
    #pragma unroll
    for (int k = 0; k < 4; k++) {
        int row = r0 + rq + 4 * k;
        float v = acc[k];
        out[row * Dd + c] = v;
        unsigned short hi;
        asm("cvt.rn.f16.f32 %0, %1;" : "=h"(hi) : "f"(v));
        g_xT_hi[y][(size_t)c * Nn + row] = hi;
    }

    // fused a-projection: row dots with a1=av[0..63], a2=av[64..127]
    float a1c = av[c], a2c = av[64 + c];
    int w = tid >> 5, lane = tid & 31;
    #pragma unroll
    for (int k = 0; k < 4; k++) {
        float p1 = acc[k] * a1c;
        float p2 = acc[k] * a2c;
        #pragma unroll
        for (int o = 16; o; o >>= 1) {
            p1 += __shfl_down_sync(0xffffffffu, p1, o);
            p2 += __shfl_down_sync(0xffffffffu, p2, o);
        }
        if (lane == 0) { s_red[w][k][0] = p1; s_red[w][k][1] = p2; }
    }
    __syncthreads();
    if (tid < 32) {
        int m = tid >> 3, k = (tid >> 1) & 3, pl = tid & 1;
        int row = r0 + m + 4 * k;
        float val = (s_red[2 * m][k][pl] + s_red[2 * m + 1][k][pl]) * LOG2E;
        if (pl == 0) {
            if (y == 0) g_s1[row] = val; else g_t1[row] = val;
        } else {
            if (y == 0) g_s2[row] = val; else g_t2[row] = val;
            g_fb2[y][row] = ex2(val);
            g_fd2[y][row] = ex2(0.01f * val);
        }
    }
}

// ---------------- P3: maxes ---------------------------------------------------
__global__ void max_kernel() {
    __shared__ float sm[512];
    int tid = threadIdx.x;
    float m1 = -1e30f, m2 = -1e30f;
    for (int i = tid; i < Nn; i += 256) {
        m1 = fmaxf(m1, g_t2[i]);
        m2 = fmaxf(m2, g_s2[i]);
    }
    sm[tid] = m1; sm[256 + tid] = m2;
    __syncthreads();
    for (int s = 128; s; s >>= 1) {
        if (tid < s) {
            sm[tid]       = fmaxf(sm[tid],       sm[tid + s]);
            sm[256 + tid] = fmaxf(sm[256 + tid], sm[256 + tid + s]);
        }
        __syncthreads();
    }
    if (tid == 0) { g_max2[0] = sm[0]; g_max2[1] = sm[256]; }
}

// ---------------- main attention: single-fp16 planes, 9 mma / chunk ----------
__global__ void __launch_bounds__(256, 3)
attn_kernel() {
    __shared__ __align__(16) char smc[16384 + 2048];   // 2x8KB B + 2x1KB bits
    uint32_t smb = smem_u32(smc);

    int p = blockIdx.y, sp = blockIdx.z;
    int i0 = blockIdx.x * TI;
    int jbase = sp * JCH;
    const float* sv = p ? g_t1 : g_s1;
    const float* tv = p ? g_s2 : g_t2;
    const float* fbv = g_fb2[p ^ 1];
    const float* fdv = g_fd2[p ^ 1];
    const unsigned short* XH = g_xT_hi[p];
    float M = g_max2[p];

    int tid = threadIdx.x, wid = tid >> 5, lane = tid & 31;
    int r = lane >> 2, c = lane & 3;
    int iA = i0 + wid * 16 + r;
    int iB = iA + 8;

    float sA = sv[iA], sB = sv[iB];
    float mA = leaky(sA + M), mB = leaky(sB + M);
    float EA = ex2(sA - mA), CA = ex2(0.01f * sA - mA);
    float EB = ex2(sB - mB), CB = ex2(0.01f * sB - mB);

    // B ldmatrix addressing (XOR swizzle: col ^ ((row&7)<<4))
    uint32_t bSel = ((lane >> 3) & 1) * 16;
    uint32_t bSwz = (lane & 7) << 4;
    uint32_t bBase = smb + ((lane & 7) + ((lane >> 4) & 1) * 8) * 128;

    // B staging indices
    int sd = tid >> 2, scc = tid & 3;
    uint32_t sSwz = (sd & 7) << 4;
    uint32_t sRow = sd * 128;
    uint32_t so1 = sRow + ((scc * 16) ^ sSwz);
    uint32_t so2 = sRow + (((scc + 4) * 16) ^ sSwz);

    const uint32_t ONE2 = 0x3C003C00u;   // fp16x2 {1.0, 1.0}
    const uint32_t WDS = Nn / 32;

    float acc[8][4];
    float den[4];
    #pragma unroll
    for (int n = 0; n < 8; n++)
        #pragma unroll
        for (int q = 0; q < 4; q++) acc[n][q] = 0.f;
    #pragma unroll
    for (int q = 0; q < 4; q++) den[q] = 0.f;

    // ---- stage tile 0 into buffer 0 (cp.async) ----
    {
        const char* srch = (const char*)(XH + (size_t)sd * Nn + jbase);
        cpa16(smb + so1, srch + scc * 16);
        cpa16(smb + so2, srch + (scc + 4) * 16);
        if (p == 0) {
            if (tid < TI) cpa8(smb + BITS_OFF + tid * 8,
                               g_adjB + (size_t)(i0 + tid) * WDS + (jbase >> 5));
        } else {
            if (tid < TJ) cpa16(smb + BITS_OFF + tid * 16,
                                g_adjB + (size_t)(jbase + tid) * WDS + (i0 >> 5));
        }
        CP_COMMIT();
        CP_WAIT0();
    }
    __syncthreads();

    for (int jt = 0; jt < NTILE; jt++) {
        int b = jt & 1;
        int j0 = jbase + jt * TJ;
        uint32_t bufB = bBase + b * 8192;
        const char* bitsCur = smc + BITS_OFF + b * 1024;

        // ---- prefetch next tile into the other buffer (async) ----
        if (jt + 1 < NTILE) {
            int jn = j0 + TJ;
            uint32_t ob = (b ^ 1);
            const char* srch = (const char*)(XH + (size_t)sd * Nn + jn);
            cpa16(smb + ob * 8192 + so1, srch + scc * 16);
            cpa16(smb + ob * 8192 + so2, srch + (scc + 4) * 16);
            if (p == 0) {
                if (tid < TI) cpa8(smb + BITS_OFF + ob * 1024 + tid * 8,
                                   g_adjB + (size_t)(i0 + tid) * WDS + (jn >> 5));
            } else {
                if (tid < TJ) cpa16(smb + BITS_OFF + ob * 1024 + tid * 16,
                                    g_adjB + (size_t)(jn + tid) * WDS + (i0 >> 5));
            }
            CP_COMMIT();
        }

        // ---- mask words for this tile ----
        uint2 vA, vB;
        int wsel = wid >> 1;
        int bitA = ((wid & 1) << 4) + r;
        if (p == 0) {
            vA = *(const uint2*)(bitsCur + (wid * 16 + r) * 8);
            vB = *(const uint2*)(bitsCur + (wid * 16 + r + 8) * 8);
        }

        // ---- per K-chunk: build fp16 A frags in regs, mma ----
        #pragma unroll
        for (int k = 0; k < 4; k++) {
            int jc = j0 + 16 * k + 2 * c;
            float2 t12  = *(const float2*)(tv + jc);
            float2 t34  = *(const float2*)(tv + jc + 8);
            float2 fb12 = *(const float2*)(fbv + jc);
            float2 fb34 = *(const float2*)(fbv + jc + 8);
            float2 fd12 = *(const float2*)(fdv + jc);
            float2 fd34 = *(const float2*)(fdv + jc + 8);

            float w0, w1, w2, w3, w4, w5, w6, w7;
            if (p == 0) {
                uint32_t qA = (k < 2) ? vA.x : vA.y;
                uint32_t qB = (k < 2) ? vB.x : vB.y;
                int b0 = ((k & 1) << 4) + 2 * c;
                w0 = wgen2(sA, EA, CA, t12.x, fb12.x, fd12.x, qA, b0);
                w1 = wgen2(sA, EA, CA, t12.y, fb12.y, fd12.y, qA, b0 + 1);
                w2 = wgen2(sA, EA, CA, t34.x, fb34.x, fd34.x, qA, b0 + 8);
                w3 = wgen2(sA, EA, CA, t34.y, fb34.y, fd34.y, qA, b0 + 9);
                w4 = wgen2(sB, EB, CB, t12.x, fb12.x, fd12.x, qB, b0);
                w5 = wgen2(sB, EB, CB, t12.y, fb12.y, fd12.y, qB, b0 + 1);
                w6 = wgen2(sB, EB, CB, t34.x, fb34.x, fd34.x, qB, b0 + 8);
                w7 = wgen2(sB, EB, CB, t34.y, fb34.y, fd34.y, qB, b0 + 9);
            } else {
                int rowb = 16 * k + 2 * c;
                uint32_t q0 = *(const uint32_t*)(bitsCur + (rowb    ) * 16 + wsel * 4);
                uint32_t q1 = *(const uint32_t*)(bitsCur + (rowb + 1) * 16 + wsel * 4);
                uint32_t q2 = *(const uint32_t*)(bitsCur + (rowb + 8) * 16 + wsel * 4);
                uint32_t q3 = *(const uint32_t*)(bitsCur + (rowb + 9) * 16 + wsel * 4);
                w0 = wgen2(sA, EA, CA, t12.x, fb12.x, fd12.x, q0, bitA);
                w1 = wgen2(sA, EA, CA, t12.y, fb12.y, fd12.y, q1, bitA);
                w2 = wgen2(sA, EA, CA, t34.x, fb34.x, fd34.x, q2, bitA);
                w3 = wgen2(sA, EA, CA, t34.y, fb34.y, fd34.y, q3, bitA);
                w4 = wgen2(sB, EB, CB, t12.x, fb12.x, fd12.x, q0, bitA + 8);
                w5 = wgen2(sB, EB, CB, t12.y, fb12.y, fd12.y, q1, bitA + 8);
                w6 = wgen2(sB, EB, CB, t34.x, fb34.x, fd34.x, q2, bitA + 8);
                w7 = wgen2(sB, EB, CB, t34.y, fb34.y, fd34.y, q3, bitA + 8);
            }

            uint32_t ah[4];
            ah[0] = hpack(w0, w1);
            ah[1] = hpack(w4, w5);
            ah[2] = hpack(w2, w3);
            ah[3] = hpack(w6, w7);

            mma16816(den, ah, ONE2, ONE2);

            #pragma unroll
            for (int nn = 0; nn < 4; nn++) {
                uint32_t bh[4];
                uint32_t boff = nn * 2048 + ((bSel + 32 * k) ^ bSwz);
                ldsm4(bh, bufB + boff);
                mma16816(acc[2 * nn],     ah, bh[0], bh[1]);
                mma16816(acc[2 * nn + 1], ah, bh[2], bh[3]);
            }
        }
        CP_WAIT0();
        __syncthreads();
    }

    // ---- write partials ----
    int buf = p * SPLITS + sp;
    int tg = lane & 3;
    float* nump = g_pnum + (size_t)buf * Nn * Dd;
    #pragma unroll
    for (int n = 0; n < 8; n++) {
        int col = n * 8 + tg * 2;
        *(float2*)(nump + (size_t)iA * Dd + col) = make_float2(acc[n][0], acc[n][1]);
        *(float2*)(nump + (size_t)iB * Dd + col) = make_float2(acc[n][2], acc[n][3]);
    }
    if (tg == 0) {
        g_pden[(size_t)buf * Nn + iA] = den[0];
        g_pden[(size_t)buf * Nn + iB] = den[2];
    }
}

// ---------------- finish: sum partials, normalize, bias + ELU ----------------
__global__ void finish_kernel(const float* __restrict__ bs, const float* __restrict__ bt,
                              float* __restrict__ out) {
    int warp = threadIdx.x >> 5, lane = threadIdx.x & 31;
    int rg = blockIdx.x * 8 + warp;
    int p = rg >> 13;
    int i = rg & (Nn - 1);
    const float* bias = p ? bt : bs;

    float2 acc = make_float2(0.f, 0.f);
    #pragma unroll
    for (int s = 0; s < SPLITS; s++) {
        const float2* np = (const float2*)(g_pnum + ((size_t)(p * SPLITS + s) * Nn + i) * Dd);
        float2 v = np[lane];
        acc.x += v.x; acc.y += v.y;
    }
    float den = (lane < SPLITS) ? g_pden[(size_t)(p * SPLITS + lane) * Nn + i] : 0.f;
    #pragma unroll
    for (int o = 16; o; o >>= 1) den += __shfl_xor_sync(0xffffffffu, den, o);
    float inv = 1.f / den;

    float v0 = acc.x * inv + bias[2 * lane];
    float v1 = acc.y * inv + bias[2 * lane + 1];
    v0 = (v0 > 0.f) ? v0 : expm1f(v0);
    v1 = (v1 > 0.f) ? v1 : expm1f(v1);
    ((float2*)(out + (size_t)rg * Dd))[lane] = make_float2(v0, v1);
}

// ---------------- launch ------------------------------------------------------
extern "C" void kernel_launch(void* const* d_in, const int* in_sizes, int n_in,
                              void* d_out, int out_size) {
    const float* xs  = (const float*)d_in[0];
    const float* xt  = (const float*)d_in[1];
    const int*   adj = (const int*)  d_in[2];
    const float* ws  = (const float*)d_in[3];
    const float* wt  = (const float*)d_in[4];
    const float* a   = (const float*)d_in[5];
    const float* bs  = (const float*)d_in[6];
    const float* bt  = (const float*)d_in[7];
    float* out = (float*)d_out;   // [2, 8192, 64]

    pack_kernel<<<Nn, 256>>>(adj);
    proj_kernel<<<dim3(Nn / 16, 2), 256>>>(xs, xt, ws, wt, a);
    max_kernel<<<1, 256>>>();
    attn_kernel<<<dim3(Nn / TI, 2, SPLITS), 256>>>();
    finish_kernel<<<(2 * Nn) / 8, 256>>>(bs, bt, out);
}

// round 15
// speedup vs baseline: 1.3555x; 1.0956x over previous
#include <cuda_runtime.h>
#include <math.h>
#include <stdint.h>

#define Nn 8192
#define Dd 64
#define IN_F 128
#define TI 256
#define TJ 64
#define SPLITS 16
#define JCH (Nn / SPLITS)     // 512
#define NTILE (JCH / TJ)      // 8
#define LOG2E 1.4426950408889634f

#define BITS_OFF 16384        // smem: 2x8KB B planes, then 2x2KB mask blocks

// ---------------- device scratch ---------------------------------------------
__device__ float g_xw_s[Nn * Dd];
__device__ float g_xw_t[Nn * Dd];
__device__ float g_s1[Nn], g_s2[Nn], g_t1[Nn], g_t2[Nn];   // pre-scaled by log2e
__device__ float4 g_ffd[2][Nn / 2];   // interleaved {fb,fd} pairs, 16B aligned
__device__ float g_max2[2];
__device__ unsigned short g_xT_hi[2][Dd * Nn];   // fp16 plane [side][d][j]
__device__ float g_pnum[2 * SPLITS * Nn * Dd];
__device__ float g_pden[2 * SPLITS * Nn];
__device__ uint32_t g_adjB[(size_t)Nn * (Nn / 32)];   // 8 MB bit-packed adjacency

// ---------------- helpers -----------------------------------------------------
__device__ __forceinline__ uint32_t smem_u32(const void* p) {
    uint32_t a;
    asm("{ .reg .u64 t; cvta.to.shared.u64 t, %1; cvt.u32.u64 %0, t; }" : "=r"(a) : "l"(p));
    return a;
}
__device__ __forceinline__ float leaky(float z) { return fmaxf(z, 0.01f * z); }
__device__ __forceinline__ float ex2(float x) {
    float r; asm("ex2.approx.f32 %0, %1;" : "=f"(r) : "f"(x)); return r;
}
__device__ __forceinline__ uint32_t hpack(float w0, float w1) {
    uint32_t r; asm("cvt.rn.f16x2.f32 %0, %1, %2;" : "=r"(r) : "f"(w1), "f"(w0)); return r;
}
__device__ __forceinline__ void ldsm4(uint32_t* r, uint32_t addr) {
    asm volatile("ldmatrix.sync.aligned.m8n8.x4.shared.b16 {%0,%1,%2,%3}, [%4];"
        : "=r"(r[0]), "=r"(r[1]), "=r"(r[2]), "=r"(r[3]) : "r"(addr));
}
__device__ __forceinline__ void mma16816(float* d, const uint32_t* a, uint32_t b0, uint32_t b1) {
    asm volatile(
        "mma.sync.aligned.m16n8k16.row.col.f32.f16.f16.f32 "
        "{%0,%1,%2,%3},{%4,%5,%6,%7},{%8,%9},{%0,%1,%2,%3};"
        : "+f"(d[0]), "+f"(d[1]), "+f"(d[2]), "+f"(d[3])
        : "r"(a[0]), "r"(a[1]), "r"(a[2]), "r"(a[3]), "r"(b0), "r"(b1));
}
__device__ __forceinline__ void cpa16(uint32_t d, const void* s) {
    asm volatile("cp.async.cg.shared.global [%0], [%1], 16;" :: "r"(d), "l"(s));
}
__device__ __forceinline__ void cpa8(uint32_t d, const void* s) {
    asm volatile("cp.async.ca.shared.global [%0], [%1], 8;" :: "r"(d), "l"(s));
}
#define CP_COMMIT() asm volatile("cp.async.commit_group;" ::: "memory")
#define CP_WAIT0()  asm volatile("cp.async.wait_group 0;" ::: "memory")

// threshold-form masked weight: w = (fb>=T ? E*fb : C*fd), masked by bit
__device__ __forceinline__ float wgen3(float E, float C, float T,
                                       float fb, float fd, uint32_t q, int bit) {
    float w = (fb >= T) ? (E * fb) : (C * fd);
    return ((q >> bit) & 1u) ? w : 0.f;
}

// ---------------- P0: pack adjacency rows to bits ----------------------------
__global__ void pack_kernel(const int* __restrict__ adj) {
    int i = blockIdx.x;
    int w8 = threadIdx.x >> 5, lane = threadIdx.x & 31;
    const int* row = adj + (size_t)i * Nn;
    uint32_t mine = 0;
    #pragma unroll 4
    for (int k = 0; k < 32; k++) {
        int word = w8 * 32 + k;
        uint32_t b = __ballot_sync(0xffffffffu, row[word * 32 + lane] > 0);
        if (lane == k) mine = b;
    }
    g_adjB[(size_t)i * (Nn / 32) + w8 * 32 + lane] = mine;
}

// ---------------- P1: xw = x @ W + fp16 plane + a-projections (fused) -------
__global__ void proj_kernel(const float* __restrict__ xs, const float* __restrict__ xt,
                            const float* __restrict__ ws, const float* __restrict__ wt,
                            const float* __restrict__ av) {
    int y = blockIdx.y;
    const float* x = y ? xt : xs;
    const float* W = y ? wt : ws;
    float* out = y ? g_xw_t : g_xw_s;

    __shared__ float Wsm[IN_F * Dd];
    __shared__ float xsm[16 * IN_F];
    __shared__ float s_red[8][4][2];

    int tid = threadIdx.x;
    const float4* W4 = (const float4*)W;
    float4* Ws4 = (float4*)Wsm;
    for (int k = tid; k < IN_F * Dd / 4; k += 256) Ws4[k] = W4[k];

    int r0 = blockIdx.x * 16;
    const float4* x4 = (const float4*)(x + r0 * IN_F);
    float4* xs4 = (float4*)xsm;
    for (int k = tid; k < 16 * IN_F / 4; k += 256) xs4[k] = x4[k];
    __syncthreads();

    int c = tid & 63, rq = tid >> 6;
    float acc[4] = {0.f, 0.f, 0.f, 0.f};
    #pragma unroll 4
    for (int kk = 0; kk < IN_F; kk++) {
        float wv = Wsm[kk * Dd + c];
        #pragma unroll
        for (int k = 0; k < 4; k++)
            acc[k] += xsm[(rq + 4 * k) * IN_F + kk] * wv;
    }
    #pragma unroll
    for (int k = 0; k < 4; k++) {
        int row = r0 + rq + 4 * k;
        float v = acc[k];
        out[row * Dd + c] = v;
        unsigned short hi;
        asm("cvt.rn.f16.f32 %0, %1;" : "=h"(hi) : "f"(v));
        g_xT_hi[y][(size_t)c * Nn + row] = hi;
    }

    // fused a-projection
    float a1c = av[c], a2c = av[64 + c];
    int w = tid >> 5, lane = tid & 31;
    #pragma unroll
    for (int k = 0; k < 4; k++) {
        float p1 = acc[k] * a1c;
        float p2 = acc[k] * a2c;
        #pragma unroll
        for (int o = 16; o; o >>= 1) {
            p1 += __shfl_down_sync(0xffffffffu, p1, o);
            p2 += __shfl_down_sync(0xffffffffu, p2, o);
        }
        if (lane == 0) { s_red[w][k][0] = p1; s_red[w][k][1] = p2; }
    }
    __syncthreads();
    if (tid < 32) {
        int m = tid >> 3, k = (tid >> 1) & 3, pl = tid & 1;
        int row = r0 + m + 4 * k;
        float val = (s_red[2 * m][k][pl] + s_red[2 * m + 1][k][pl]) * LOG2E;
        if (pl == 0) {
            if (y == 0) g_s1[row] = val; else g_t1[row] = val;
        } else {
            if (y == 0) g_s2[row] = val; else g_t2[row] = val;
            float* fp = (float*)g_ffd[y];
            fp[2 * row]     = ex2(val);
            fp[2 * row + 1] = ex2(0.01f * val);
        }
    }
}

// ---------------- main attention: 32 rows/warp, threshold weights ------------
__global__ void __launch_bounds__(256, 2)
attn_kernel() {
    __shared__ __align__(16) char smc[16384 + 4096];   // 2x8KB B + 2x2KB bits
    uint32_t smb = smem_u32(smc);

    int p = blockIdx.y, sp = blockIdx.z;
    int i0 = blockIdx.x * TI;
    int jbase = sp * JCH;
    const float* sv = p ? g_t1 : g_s1;
    const float4* ffdv = g_ffd[p ^ 1];
    const unsigned short* XH = g_xT_hi[p];
    float M = g_max2[p];

    int tid = threadIdx.x, wid = tid >> 5, lane = tid & 31;
    int r = lane >> 2, c = lane & 3;

    // 4 row-variants per thread: u = f*2+h -> row i0 + wid*32 + f*16 + h*8 + r
    float Ee[4], Cc[4], Tt[4];
    #pragma unroll
    for (int u = 0; u < 4; u++) {
        int row = i0 + wid * 32 + (u >> 1) * 16 + (u & 1) * 8 + r;
        float s = sv[row];
        float m = leaky(s + M);
        Ee[u] = ex2(s - m);
        Cc[u] = ex2(0.01f * s - m);
        Tt[u] = ex2(-s);
    }

    // B ldmatrix addressing (XOR swizzle: col ^ ((row&7)<<4))
    uint32_t bSel = ((lane >> 3) & 1) * 16;
    uint32_t bSwz = (lane & 7) << 4;
    uint32_t bBase = smb + ((lane & 7) + ((lane >> 4) & 1) * 8) * 128;

    // B staging indices
    int sd = tid >> 2, scc = tid & 3;
    uint32_t sSwz = (sd & 7) << 4;
    uint32_t sRow = sd * 128;
    uint32_t so1 = sRow + ((scc * 16) ^ sSwz);
    uint32_t so2 = sRow + (((scc + 4) * 16) ^ sSwz);

    const uint32_t ONE2 = 0x3C003C00u;   // fp16x2 {1.0, 1.0}
    const uint32_t WDS = Nn / 32;

    float acc[16][4];
    float den[2][4];
    #pragma unroll
    for (int n = 0; n < 16; n++)
        #pragma unroll
        for (int q = 0; q < 4; q++) acc[n][q] = 0.f;
    #pragma unroll
    for (int f = 0; f < 2; f++)
        #pragma unroll
        for (int q = 0; q < 4; q++) den[f][q] = 0.f;

    // ---- stage tile 0 into buffer 0 ----
    {
        const char* srch = (const char*)(XH + (size_t)sd * Nn + jbase);
        cpa16(smb + so1, srch + scc * 16);
        cpa16(smb + so2, srch + (scc + 4) * 16);
        if (p == 0) {
            cpa8(smb + BITS_OFF + tid * 8,
                 g_adjB + (size_t)(i0 + tid) * WDS + (jbase >> 5));
        } else {
            if (tid < 128) {
                int jr = tid >> 1, part = tid & 1;
                cpa16(smb + BITS_OFF + jr * 32 + part * 16,
                      g_adjB + (size_t)(jbase + jr) * WDS + (i0 >> 5) + part * 4);
            }
        }
        CP_COMMIT();
        CP_WAIT0();
    }
    __syncthreads();

    for (int jt = 0; jt < NTILE; jt++) {
        int b = jt & 1;
        int j0 = jbase + jt * TJ;
        uint32_t bufB = bBase + b * 8192;
        const char* bitsCur = smc + BITS_OFF + b * 2048;

        // ---- prefetch next tile ----
        if (jt + 1 < NTILE) {
            int jn = j0 + TJ;
            uint32_t ob = (b ^ 1);
            const char* srch = (const char*)(XH + (size_t)sd * Nn + jn);
            cpa16(smb + ob * 8192 + so1, srch + scc * 16);
            cpa16(smb + ob * 8192 + so2, srch + (scc + 4) * 16);
            if (p == 0) {
                cpa8(smb + BITS_OFF + ob * 2048 + tid * 8,
                     g_adjB + (size_t)(i0 + tid) * WDS + (jn >> 5));
            } else {
                if (tid < 128) {
                    int jr = tid >> 1, part = tid & 1;
                    cpa16(smb + BITS_OFF + ob * 2048 + jr * 32 + part * 16,
                          g_adjB + (size_t)(jn + jr) * WDS + (i0 >> 5) + part * 4);
                }
            }
            CP_COMMIT();
        }

        // ---- mask words for this tile (p==0: one uint2 per row-variant) ----
        uint2 v[4];
        if (p == 0) {
            #pragma unroll
            for (int u = 0; u < 4; u++)
                v[u] = *(const uint2*)(bitsCur +
                        (wid * 32 + (u >> 1) * 16 + (u & 1) * 8 + r) * 8);
        }

        // ---- per K-chunk ----
        #pragma unroll
        for (int k = 0; k < 4; k++) {
            int jc = j0 + 16 * k + 2 * c;
            float4 fA = ffdv[jc >> 1];         // {fb(jc), fd(jc), fb(jc+1), fd(jc+1)}
            float4 fB = ffdv[(jc >> 1) + 4];   // {fb(jc+8), ... fb(jc+9), ...}

            // B fragments (shared by both A-frags)
            uint32_t bh[4][4];
            #pragma unroll
            for (int nn = 0; nn < 4; nn++) {
                uint32_t boff = nn * 2048 + ((bSel + 32 * k) ^ bSwz);
                ldsm4(bh[nn], bufB + boff);
            }

            uint32_t q0, q1, q2, q3;
            int b0 = ((k & 1) << 4) + 2 * c;   // p==0 bit base
            if (p == 1) {
                int rowb = 16 * k + 2 * c;
                q0 = *(const uint32_t*)(bitsCur + (rowb    ) * 32 + wid * 4);
                q1 = *(const uint32_t*)(bitsCur + (rowb + 1) * 32 + wid * 4);
                q2 = *(const uint32_t*)(bitsCur + (rowb + 8) * 32 + wid * 4);
                q3 = *(const uint32_t*)(bitsCur + (rowb + 9) * 32 + wid * 4);
            }

            #pragma unroll
            for (int f = 0; f < 2; f++) {
                int ua = 2 * f, ub = 2 * f + 1;
                float w0, w1, w2, w3, w4, w5, w6, w7;
                if (p == 0) {
                    uint32_t qA = (k < 2) ? v[ua].x : v[ua].y;
                    uint32_t qB = (k < 2) ? v[ub].x : v[ub].y;
                    w0 = wgen3(Ee[ua], Cc[ua], Tt[ua], fA.x, fA.y, qA, b0);
                    w1 = wgen3(Ee[ua], Cc[ua], Tt[ua], fA.z, fA.w, qA, b0 + 1);
                    w2 = wgen3(Ee[ua], Cc[ua], Tt[ua], fB.x, fB.y, qA, b0 + 8);
                    w3 = wgen3(Ee[ua], Cc[ua], Tt[ua], fB.z, fB.w, qA, b0 + 9);
                    w4 = wgen3(Ee[ub], Cc[ub], Tt[ub], fA.x, fA.y, qB, b0);
                    w5 = wgen3(Ee[ub], Cc[ub], Tt[ub], fA.z, fA.w, qB, b0 + 1);
                    w6 = wgen3(Ee[ub], Cc[ub], Tt[ub], fB.x, fB.y, qB, b0 + 8);
                    w7 = wgen3(Ee[ub], Cc[ub], Tt[ub], fB.z, fB.w, qB, b0 + 9);
                } else {
                    int bitA = f * 16 + r;       // row u=2f   (h=0)
                    int bitB = bitA + 8;         // row u=2f+1 (h=1)
                    w0 = wgen3(Ee[ua], Cc[ua], Tt[ua], fA.x, fA.y, q0, bitA);
                    w1 = wgen3(Ee[ua], Cc[ua], Tt[ua], fA.z, fA.w, q1, bitA);
                    w2 = wgen3(Ee[ua], Cc[ua], Tt[ua], fB.x, fB.y, q2, bitA);
                    w3 = wgen3(Ee[ua], Cc[ua], Tt[ua], fB.z, fB.w, q3, bitA);
                    w4 = wgen3(Ee[ub], Cc[ub], Tt[ub], fA.x, fA.y, q0, bitB);
                    w5 = wgen3(Ee[ub], Cc[ub], Tt[ub], fA.z, fA.w, q1, bitB);
                    w6 = wgen3(Ee[ub], Cc[ub], Tt[ub], fB.x, fB.y, q2, bitB);
                    w7 = wgen3(Ee[ub], Cc[ub], Tt[ub], fB.z, fB.w, q3, bitB);
                }

                uint32_t ah[4];
                ah[0] = hpack(w0, w1);
                ah[1] = hpack(w4, w5);
                ah[2] = hpack(w2, w3);
                ah[3] = hpack(w6, w7);

                mma16816(den[f], ah, ONE2, ONE2);

                #pragma unroll
                for (int nn = 0; nn < 4; nn++) {
                    mma16816(acc[f * 8 + 2 * nn],     ah, bh[nn][0], bh[nn][1]);
                    mma16816(acc[f * 8 + 2 * nn + 1], ah, bh[nn][2], bh[nn][3]);
                }
            }
        }
        CP_WAIT0();
        __syncthreads();
    }

    // ---- write partials ----
    int buf = p * SPLITS + sp;
    int tg = lane & 3;
    float* nump = g_pnum + (size_t)buf * Nn * Dd;
    #pragma unroll
    for (int f = 0; f < 2; f++) {
        int ia = i0 + wid * 32 + f * 16 + r;
        int ib = ia + 8;
        #pragma unroll
        for (int n = 0; n < 8; n++) {
            int col = n * 8 + tg * 2;
            *(float2*)(nump + (size_t)ia * Dd + col) =
                make_float2(acc[f * 8 + n][0], acc[f * 8 + n][1]);
            *(float2*)(nump + (size_t)ib * Dd + col) =
                make_float2(acc[f * 8 + n][2], acc[f * 8 + n][3]);
        }
        if (tg == 0) {
            g_pden[(size_t)buf * Nn + ia] = den[f][0];
            g_pden[(size_t)buf * Nn + ib] = den[f][2];
        }
    }
}

// ---------------- P3: maxes ---------------------------------------------------
__global__ void max_kernel() {
    __shared__ float sm[512];
    int tid = threadIdx.x;
    float m1 = -1e30f, m2 = -1e30f;
    for (int i = tid; i < Nn; i += 256) {
        m1 = fmaxf(m1, g_t2[i]);
        m2 = fmaxf(m2, g_s2[i]);
    }
    sm[tid] = m1; sm[256 + tid] = m2;
    __syncthreads();
    for (int s = 128; s; s >>= 1) {
        if (tid < s) {
            sm[tid]       = fmaxf(sm[tid],       sm[tid + s]);
            sm[256 + tid] = fmaxf(sm[256 + tid], sm[256 + tid + s]);
        }
        __syncthreads();
    }
    if (tid == 0) { g_max2[0] = sm[0]; g_max2[1] = sm[256]; }
}

// ---------------- finish: sum partials, normalize, bias + ELU ----------------
__global__ void finish_kernel(const float* __restrict__ bs, const float* __restrict__ bt,
                              float* __restrict__ out) {
    int warp = threadIdx.x >> 5, lane = threadIdx.x & 31;
    int rg = blockIdx.x * 8 + warp;
    int p = rg >> 13;
    int i = rg & (Nn - 1);
    const float* bias = p ? bt : bs;

    float2 acc = make_float2(0.f, 0.f);
    #pragma unroll
    for (int s = 0; s < SPLITS; s++) {
        const float2* np = (const float2*)(g_pnum + ((size_t)(p * SPLITS + s) * Nn + i) * Dd);
        float2 v = np[lane];
        acc.x += v.x; acc.y += v.y;
    }
    float den = (lane < SPLITS) ? g_pden[(size_t)(p * SPLITS + lane) * Nn + i] : 0.f;
    #pragma unroll
    for (int o = 16; o; o >>= 1) den += __shfl_xor_sync(0xffffffffu, den, o);
    float inv = 1.f / den;

    float v0 = acc.x * inv + bias[2 * lane];
    float v1 = acc.y * inv + bias[2 * lane + 1];
    v0 = (v0 > 0.f) ? v0 : expm1f(v0);
    v1 = (v1 > 0.f) ? v1 : expm1f(v1);
    ((float2*)(out + (size_t)rg * Dd))[lane] = make_float2(v0, v1);
}

// ---------------- launch ------------------------------------------------------
extern "C" void kernel_launch(void* const* d_in, const int* in_sizes, int n_in,
                              void* d_out, int out_size) {
    const float* xs  = (const float*)d_in[0];
    const float* xt  = (const float*)d_in[1];
    const int*   adj = (const int*)  d_in[2];
    const float* ws  = (const float*)d_in[3];
    const float* wt  = (const float*)d_in[4];
    const float* a   = (const float*)d_in[5];
    const float* bs  = (const float*)d_in[6];
    const float* bt  = (const float*)d_in[7];
    float* out = (float*)d_out;   // [2, 8192, 64]

    pack_kernel<<<Nn, 256>>>(adj);
    proj_kernel<<<dim3(Nn / 16, 2), 256>>>(xs, xt, ws, wt, a);
    max_kernel<<<1, 256>>>();
    attn_kernel<<<dim3(Nn / TI, 2, SPLITS), 256>>>();
    finish_kernel<<<(2 * Nn) / 8, 256>>>(bs, bt, out);
}